// round 2
// baseline (speedup 1.0000x reference)
#include <cuda_runtime.h>
#include <math.h>

#define D_MODEL 512
#define NHEAD 8
#define HEAD_DIM 64
#define D_FF 2048
#define BATCH 4
#define SEQ 2048
#define NTOK (BATCH * SEQ)   // 8192
#define EPS 1e-5f

// ---------------- scratch (device globals; no allocation allowed) ----------------
__device__ float g_h [NTOK * D_MODEL];
__device__ float g_q [NTOK * D_MODEL];
__device__ float g_k [NTOK * D_MODEL];
__device__ float g_v [NTOK * D_MODEL];
__device__ float g_o [NTOK * D_MODEL];
__device__ float g_x1[NTOK * D_MODEL];
__device__ float g_h2[NTOK * D_MODEL];
__device__ float g_ff[NTOK * D_FF];

// ---------------- LayerNorm: one block (128 threads) per token ----------------
__global__ __launch_bounds__(128)
void ln_kernel(const float* __restrict__ x, const float* __restrict__ w,
               const float* __restrict__ b, float* __restrict__ out) {
    int tok = blockIdx.x;
    int tid = threadIdx.x;                       // 0..127, 4 floats each
    const float4* xv = (const float4*)(x + (size_t)tok * D_MODEL);
    float4 v = xv[tid];
    float s  = v.x + v.y + v.z + v.w;
    float sq = v.x*v.x + v.y*v.y + v.z*v.z + v.w*v.w;
    #pragma unroll
    for (int off = 16; off; off >>= 1) {
        s  += __shfl_xor_sync(0xffffffffu, s,  off);
        sq += __shfl_xor_sync(0xffffffffu, sq, off);
    }
    __shared__ float ss[4], ssq[4];
    if ((tid & 31) == 0) { ss[tid >> 5] = s; ssq[tid >> 5] = sq; }
    __syncthreads();
    s  = ss[0]  + ss[1]  + ss[2]  + ss[3];
    sq = ssq[0] + ssq[1] + ssq[2] + ssq[3];
    float mu  = s * (1.0f / D_MODEL);
    float var = sq * (1.0f / D_MODEL) - mu * mu;
    float inv = rsqrtf(var + EPS);
    float4 wv = ((const float4*)w)[tid];
    float4 bv = ((const float4*)b)[tid];
    float4 o;
    o.x = (v.x - mu) * inv * wv.x + bv.x;
    o.y = (v.y - mu) * inv * wv.y + bv.y;
    o.z = (v.z - mu) * inv * wv.z + bv.z;
    o.w = (v.w - mu) * inv * wv.w + bv.w;
    ((float4*)(out + (size_t)tok * D_MODEL))[tid] = o;
}

// ---------------- SGEMM: C = epi(A @ W + bias [, + res]) ----------------
// 128x128 tile, BK=8, 256 threads, 8x8 microtile.
// EPI: 0 = bias only, 1 = bias + exact GELU, 2 = bias + residual add
__device__ __forceinline__ float gelu_exact(float x) {
    return 0.5f * x * (1.0f + erff(x * 0.70710678118654752f));
}

template<int EPI>
__global__ __launch_bounds__(256)
void sgemm_kernel(const float* __restrict__ A, const float* __restrict__ W,
                  const float* __restrict__ bias, const float* __restrict__ res,
                  float* __restrict__ C, int M, int N, int K) {
    __shared__ float As[8][128];
    __shared__ float Bs[8][128];
    int tid = threadIdx.x;
    int m0 = blockIdx.y * 128, n0 = blockIdx.x * 128;

    int arow = tid >> 1, acol = (tid & 1) << 2;   // A tile: 128 rows x 8 k
    int brow = tid >> 5, bcol = (tid & 31) << 2;  // W tile: 8 rows x 128 cols
    const float* Aptr = A + (size_t)(m0 + arow) * K + acol;
    const float* Wptr = W + (size_t)brow * N + n0 + bcol;

    int tm = (tid >> 4) << 3;   // row offset of 8x8 microtile
    int tn = (tid & 15) << 3;

    float acc[8][8];
    #pragma unroll
    for (int i = 0; i < 8; i++)
        #pragma unroll
        for (int j = 0; j < 8; j++) acc[i][j] = 0.0f;

    for (int k0 = 0; k0 < K; k0 += 8) {
        float4 av = *(const float4*)(Aptr + k0);
        float4 bv = *(const float4*)(Wptr + (size_t)k0 * N);
        As[acol + 0][arow] = av.x;
        As[acol + 1][arow] = av.y;
        As[acol + 2][arow] = av.z;
        As[acol + 3][arow] = av.w;
        *(float4*)&Bs[brow][bcol] = bv;
        __syncthreads();
        #pragma unroll
        for (int kk = 0; kk < 8; kk++) {
            float4 a0 = *(float4*)&As[kk][tm];
            float4 a1 = *(float4*)&As[kk][tm + 4];
            float4 b0 = *(float4*)&Bs[kk][tn];
            float4 b1 = *(float4*)&Bs[kk][tn + 4];
            float a[8] = {a0.x, a0.y, a0.z, a0.w, a1.x, a1.y, a1.z, a1.w};
            float b[8] = {b0.x, b0.y, b0.z, b0.w, b1.x, b1.y, b1.z, b1.w};
            #pragma unroll
            for (int i = 0; i < 8; i++)
                #pragma unroll
                for (int j = 0; j < 8; j++)
                    acc[i][j] += a[i] * b[j];
        }
        __syncthreads();
    }

    // epilogue
    float bn[8];
    #pragma unroll
    for (int j = 0; j < 8; j++) bn[j] = bias[n0 + tn + j];
    #pragma unroll
    for (int i = 0; i < 8; i++) {
        size_t row = (size_t)(m0 + tm + i);
        #pragma unroll
        for (int j = 0; j < 8; j += 4) {
            size_t idx = row * N + n0 + tn + j;
            float c0 = acc[i][j + 0] + bn[j + 0];
            float c1 = acc[i][j + 1] + bn[j + 1];
            float c2 = acc[i][j + 2] + bn[j + 2];
            float c3 = acc[i][j + 3] + bn[j + 3];
            if (EPI == 1) {
                c0 = gelu_exact(c0); c1 = gelu_exact(c1);
                c2 = gelu_exact(c2); c3 = gelu_exact(c3);
            }
            if (EPI == 2) {
                float4 r = *(const float4*)&res[idx];
                c0 += r.x; c1 += r.y; c2 += r.z; c3 += r.w;
            }
            float4 o = make_float4(c0, c1, c2, c3);
            *(float4*)&C[idx] = o;
        }
    }
}

// ---------------- Flash attention with additive bias ----------------
// grid: (SEQ/64, NHEAD, BATCH), block 256. Q/K/V stored token-major [tok][h*64+d].
// Per block: 64 q-rows, loop over k in 64-tiles, online softmax.
// smem: Qt[64][68] (d-major), Kt[64][68] (d-major), Vs[64][64], S[64][68]
#define FL_PAD 68
__global__ __launch_bounds__(256)
void flash_kernel(const float* __restrict__ Q, const float* __restrict__ Kv,
                  const float* __restrict__ V, const float* __restrict__ bias,
                  float* __restrict__ O) {
    extern __shared__ float sm[];
    float* Qt = sm;                          // 64*68
    float* Kt = Qt + 64 * FL_PAD;            // 64*68
    float* Vs = Kt + 64 * FL_PAD;            // 64*64
    float* S  = Vs + 64 * 64;                // 64*68

    int qt = blockIdx.x;
    int h  = blockIdx.y;
    int b  = blockIdx.z;
    int tid = threadIdx.x;
    int q0 = qt * 64;
    int ty = tid >> 4, tx = tid & 15;
    int r0 = ty << 2, c0 = tx << 2;

    // load Q tile, transposed to d-major
    {
        int r  = tid >> 2;
        int dg = (tid & 3) << 4;
        const float* qrow = Q + ((size_t)(b * SEQ + q0 + r)) * D_MODEL + h * HEAD_DIM;
        #pragma unroll
        for (int ii = 0; ii < 4; ii++) {
            float4 v = *(const float4*)(qrow + dg + ii * 4);
            int d = dg + ii * 4;
            Qt[(d + 0) * FL_PAD + r] = v.x;
            Qt[(d + 1) * FL_PAD + r] = v.y;
            Qt[(d + 2) * FL_PAD + r] = v.z;
            Qt[(d + 3) * FL_PAD + r] = v.w;
        }
    }

    float m_i[4], l_i[4], o_acc[4][4];
    #pragma unroll
    for (int i = 0; i < 4; i++) {
        m_i[i] = -1e30f; l_i[i] = 0.0f;
        #pragma unroll
        for (int j = 0; j < 4; j++) o_acc[i][j] = 0.0f;
    }
    const float scale = 0.125f;  // 1/sqrt(64)

    for (int k0 = 0; k0 < SEQ; k0 += 64) {
        __syncthreads();  // previous O-phase done (also covers Qt on first iter)
        // load K (transposed) and V (row-major) tiles
        {
            int r  = tid >> 2;
            int dg = (tid & 3) << 4;
            const float* krow = Kv + ((size_t)(b * SEQ + k0 + r)) * D_MODEL + h * HEAD_DIM;
            const float* vrow = V  + ((size_t)(b * SEQ + k0 + r)) * D_MODEL + h * HEAD_DIM;
            #pragma unroll
            for (int ii = 0; ii < 4; ii++) {
                int d = dg + ii * 4;
                float4 kv = *(const float4*)(krow + d);
                Kt[(d + 0) * FL_PAD + r] = kv.x;
                Kt[(d + 1) * FL_PAD + r] = kv.y;
                Kt[(d + 2) * FL_PAD + r] = kv.z;
                Kt[(d + 3) * FL_PAD + r] = kv.w;
                float4 vv = *(const float4*)(vrow + d);
                *(float4*)&Vs[r * 64 + d] = vv;
            }
        }
        __syncthreads();

        // S = scale * Q K^T + bias
        float acc[4][4];
        #pragma unroll
        for (int i = 0; i < 4; i++)
            #pragma unroll
            for (int j = 0; j < 4; j++) acc[i][j] = 0.0f;
        #pragma unroll 8
        for (int d = 0; d < HEAD_DIM; d++) {
            float4 a = *(float4*)&Qt[d * FL_PAD + r0];
            float4 bb = *(float4*)&Kt[d * FL_PAD + c0];
            float av[4] = {a.x, a.y, a.z, a.w};
            float bvv[4] = {bb.x, bb.y, bb.z, bb.w};
            #pragma unroll
            for (int i = 0; i < 4; i++)
                #pragma unroll
                for (int j = 0; j < 4; j++)
                    acc[i][j] += av[i] * bvv[j];
        }

        // online softmax (rows split across 16 lanes, 4 cols each)
        float alpha[4];
        #pragma unroll
        for (int i = 0; i < 4; i++) {
            const float* brow = bias + ((size_t)h * SEQ + (q0 + r0 + i)) * SEQ + k0 + c0;
            float4 bb = *(const float4*)brow;
            float s0 = acc[i][0] * scale + bb.x;
            float s1 = acc[i][1] * scale + bb.y;
            float s2 = acc[i][2] * scale + bb.z;
            float s3 = acc[i][3] * scale + bb.w;
            float mx = fmaxf(fmaxf(s0, s1), fmaxf(s2, s3));
            #pragma unroll
            for (int off = 1; off < 16; off <<= 1)
                mx = fmaxf(mx, __shfl_xor_sync(0xffffffffu, mx, off));
            float m_new = fmaxf(m_i[i], mx);
            float al = __expf(m_i[i] - m_new);
            s0 = __expf(s0 - m_new);
            s1 = __expf(s1 - m_new);
            s2 = __expf(s2 - m_new);
            s3 = __expf(s3 - m_new);
            float sum = s0 + s1 + s2 + s3;
            #pragma unroll
            for (int off = 1; off < 16; off <<= 1)
                sum += __shfl_xor_sync(0xffffffffu, sum, off);
            l_i[i] = l_i[i] * al + sum;
            m_i[i] = m_new;
            alpha[i] = al;
            *(float4*)&S[(r0 + i) * FL_PAD + c0] = make_float4(s0, s1, s2, s3);
        }
        #pragma unroll
        for (int i = 0; i < 4; i++)
            #pragma unroll
            for (int j = 0; j < 4; j++) o_acc[i][j] *= alpha[i];
        __syncthreads();

        // O += P @ V
        #pragma unroll 4
        for (int j = 0; j < 64; j++) {
            float4 v = *(float4*)&Vs[j * 64 + c0];
            #pragma unroll
            for (int i = 0; i < 4; i++) {
                float p = S[(r0 + i) * FL_PAD + j];
                o_acc[i][0] += p * v.x;
                o_acc[i][1] += p * v.y;
                o_acc[i][2] += p * v.z;
                o_acc[i][3] += p * v.w;
            }
        }
    }

    // normalize and store
    #pragma unroll
    for (int i = 0; i < 4; i++) {
        float invl = 1.0f / l_i[i];
        float4 o = make_float4(o_acc[i][0] * invl, o_acc[i][1] * invl,
                               o_acc[i][2] * invl, o_acc[i][3] * invl);
        *(float4*)&O[((size_t)(b * SEQ + q0 + r0 + i)) * D_MODEL + h * HEAD_DIM + c0] = o;
    }
}

// ---------------- launch ----------------
extern "C" void kernel_launch(void* const* d_in, const int* in_sizes, int n_in,
                              void* d_out, int out_size) {
    const float* x    = (const float*)d_in[0];
    const float* ab   = (const float*)d_in[1];
    const float* ln1w = (const float*)d_in[2];
    const float* ln1b = (const float*)d_in[3];
    const float* ln2w = (const float*)d_in[4];
    const float* ln2b = (const float*)d_in[5];
    const float* wq   = (const float*)d_in[6];
    const float* bq   = (const float*)d_in[7];
    const float* wk   = (const float*)d_in[8];
    const float* bk   = (const float*)d_in[9];
    const float* wv   = (const float*)d_in[10];
    const float* bv   = (const float*)d_in[11];
    const float* wo   = (const float*)d_in[12];
    const float* bo   = (const float*)d_in[13];
    const float* w1   = (const float*)d_in[14];
    const float* b1   = (const float*)d_in[15];
    const float* w2   = (const float*)d_in[16];
    const float* b2   = (const float*)d_in[17];
    float* out = (float*)d_out;

    float *h, *q, *k, *v, *o, *x1, *h2, *ff;
    cudaGetSymbolAddress((void**)&h,  g_h);
    cudaGetSymbolAddress((void**)&q,  g_q);
    cudaGetSymbolAddress((void**)&k,  g_k);
    cudaGetSymbolAddress((void**)&v,  g_v);
    cudaGetSymbolAddress((void**)&o,  g_o);
    cudaGetSymbolAddress((void**)&x1, g_x1);
    cudaGetSymbolAddress((void**)&h2, g_h2);
    cudaGetSymbolAddress((void**)&ff, g_ff);

    const int FLASH_SMEM = (3 * 64 * FL_PAD + 64 * 64) * (int)sizeof(float);  // 68608 B
    cudaFuncSetAttribute(flash_kernel, cudaFuncAttributeMaxDynamicSharedMemorySize, FLASH_SMEM);

    dim3 gD(D_MODEL / 128, NTOK / 128);   // N=512 tiles
    dim3 gF(D_FF   / 128, NTOK / 128);    // N=2048 tiles

    // 1. h = LN1(x)
    ln_kernel<<<NTOK, 128>>>(x, ln1w, ln1b, h);
    // 2-4. q,k,v = h @ w{q,k,v} + b
    sgemm_kernel<0><<<gD, 256>>>(h, wq, bq, nullptr, q, NTOK, D_MODEL, D_MODEL);
    sgemm_kernel<0><<<gD, 256>>>(h, wk, bk, nullptr, k, NTOK, D_MODEL, D_MODEL);
    sgemm_kernel<0><<<gD, 256>>>(h, wv, bv, nullptr, v, NTOK, D_MODEL, D_MODEL);
    // 5. attention
    flash_kernel<<<dim3(SEQ / 64, NHEAD, BATCH), 256, FLASH_SMEM>>>(q, k, v, ab, o);
    // 6. x1 = x + o @ wo + bo
    sgemm_kernel<2><<<gD, 256>>>(o, wo, bo, x, x1, NTOK, D_MODEL, D_MODEL);
    // 7. h2 = LN2(x1)
    ln_kernel<<<NTOK, 128>>>(x1, ln2w, ln2b, h2);
    // 8. ff = GELU(h2 @ w1 + b1)
    sgemm_kernel<1><<<gF, 256>>>(h2, w1, b1, nullptr, ff, NTOK, D_FF, D_MODEL);
    // 9. out = x1 + ff @ w2 + b2
    sgemm_kernel<2><<<gD, 256>>>(ff, w2, b2, x1, out, NTOK, D_MODEL, D_FF);
}

// round 4
// speedup vs baseline: 1.3936x; 1.3936x over previous
#include <cuda_runtime.h>
#include <cuda_bf16.h>
#include <mma.h>
#include <math.h>
#include <cstdint>

using namespace nvcuda;

#define D_MODEL 512
#define NHEAD 8
#define HEAD_DIM 64
#define D_FF 2048
#define BATCH 4
#define SEQ 2048
#define NTOK (BATCH * SEQ)   // 8192
#define EPS 1e-5f

// ================= scratch (device globals) =================
__device__ __align__(256) float g_q [NTOK * D_MODEL];
__device__ __align__(256) float g_k [NTOK * D_MODEL];
__device__ __align__(256) float g_v [NTOK * D_MODEL];
__device__ __align__(256) float g_x1[NTOK * D_MODEL];

__device__ __align__(256) __nv_bfloat16 g_h_hi [NTOK * D_MODEL];
__device__ __align__(256) __nv_bfloat16 g_h_lo [NTOK * D_MODEL];
__device__ __align__(256) __nv_bfloat16 g_o_hi [NTOK * D_MODEL];
__device__ __align__(256) __nv_bfloat16 g_o_lo [NTOK * D_MODEL];
__device__ __align__(256) __nv_bfloat16 g_h2_hi[NTOK * D_MODEL];
__device__ __align__(256) __nv_bfloat16 g_h2_lo[NTOK * D_MODEL];
__device__ __align__(256) __nv_bfloat16 g_ff_hi[NTOK * D_FF];
__device__ __align__(256) __nv_bfloat16 g_ff_lo[NTOK * D_FF];

// transposed (N-major, K contiguous) weights as bf16 hi/lo
__device__ __align__(256) __nv_bfloat16 g_wqt_hi[D_MODEL * D_MODEL];
__device__ __align__(256) __nv_bfloat16 g_wqt_lo[D_MODEL * D_MODEL];
__device__ __align__(256) __nv_bfloat16 g_wkt_hi[D_MODEL * D_MODEL];
__device__ __align__(256) __nv_bfloat16 g_wkt_lo[D_MODEL * D_MODEL];
__device__ __align__(256) __nv_bfloat16 g_wvt_hi[D_MODEL * D_MODEL];
__device__ __align__(256) __nv_bfloat16 g_wvt_lo[D_MODEL * D_MODEL];
__device__ __align__(256) __nv_bfloat16 g_wot_hi[D_MODEL * D_MODEL];
__device__ __align__(256) __nv_bfloat16 g_wot_lo[D_MODEL * D_MODEL];
__device__ __align__(256) __nv_bfloat16 g_w1t_hi[D_FF * D_MODEL];
__device__ __align__(256) __nv_bfloat16 g_w1t_lo[D_FF * D_MODEL];
__device__ __align__(256) __nv_bfloat16 g_w2t_hi[D_MODEL * D_FF];
__device__ __align__(256) __nv_bfloat16 g_w2t_lo[D_MODEL * D_FF];

// ================= helpers =================
__device__ __forceinline__ uint32_t smem_u32(const void* p) {
    uint32_t a;
    asm("{ .reg .u64 t; cvta.to.shared.u64 t, %1; cvt.u32.u64 %0, t; }" : "=r"(a) : "l"(p));
    return a;
}
__device__ __forceinline__ void cp16(uint32_t s, const void* g) {
    asm volatile("cp.async.cg.shared.global [%0], [%1], 16;" :: "r"(s), "l"(g));
}
#define CP_COMMIT() asm volatile("cp.async.commit_group;" ::: "memory")
#define CP_WAIT(n)  asm volatile("cp.async.wait_group %0;" :: "n"(n) : "memory")

// bf16 split/pack
__device__ __forceinline__ void split_store4(__nv_bfloat16* hp, __nv_bfloat16* lp, size_t idx,
                                             float a, float b, float c, float d) {
    __nv_bfloat16 h0 = __float2bfloat16(a), h1 = __float2bfloat16(b);
    __nv_bfloat16 h2 = __float2bfloat16(c), h3 = __float2bfloat16(d);
    __nv_bfloat16 l0 = __float2bfloat16(a - __bfloat162float(h0));
    __nv_bfloat16 l1 = __float2bfloat16(b - __bfloat162float(h1));
    __nv_bfloat16 l2 = __float2bfloat16(c - __bfloat162float(h2));
    __nv_bfloat16 l3 = __float2bfloat16(d - __bfloat162float(h3));
    __nv_bfloat162 hh0 = __halves2bfloat162(h0, h1), hh1 = __halves2bfloat162(h2, h3);
    __nv_bfloat162 ll0 = __halves2bfloat162(l0, l1), ll1 = __halves2bfloat162(l2, l3);
    uint2 hu, lu;
    hu.x = *(uint32_t*)&hh0; hu.y = *(uint32_t*)&hh1;
    lu.x = *(uint32_t*)&ll0; lu.y = *(uint32_t*)&ll1;
    *(uint2*)(hp + idx) = hu;
    *(uint2*)(lp + idx) = lu;
}

__device__ __forceinline__ float gelu_exact(float x) {
    return 0.5f * x * (1.0f + erff(x * 0.70710678118654752f));
}

// ================= weight transpose + bf16 split =================
__global__ __launch_bounds__(256)
void convert_w(const float* __restrict__ W, __nv_bfloat16* __restrict__ Th,
               __nv_bfloat16* __restrict__ Tl, int K, int N) {
    __shared__ float t[32][33];
    int tx = threadIdx.x & 31, ty = threadIdx.x >> 5;
    int k0 = blockIdx.x * 32, n0 = blockIdx.y * 32;
    #pragma unroll
    for (int r = 0; r < 32; r += 8)
        t[ty + r][tx] = W[(size_t)(k0 + ty + r) * N + n0 + tx];
    __syncthreads();
    #pragma unroll
    for (int r = 0; r < 32; r += 8) {
        float v = t[tx][ty + r];
        __nv_bfloat16 h = __float2bfloat16(v);
        __nv_bfloat16 l = __float2bfloat16(v - __bfloat162float(h));
        size_t idx = (size_t)(n0 + ty + r) * K + k0 + tx;
        Th[idx] = h; Tl[idx] = l;
    }
}

// ================= LayerNorm -> bf16 hi/lo =================
__global__ __launch_bounds__(128)
void ln_kernel(const float* __restrict__ x, const float* __restrict__ w,
               const float* __restrict__ b, __nv_bfloat16* __restrict__ oh,
               __nv_bfloat16* __restrict__ ol) {
    int tok = blockIdx.x;
    int tid = threadIdx.x;
    const float4* xv = (const float4*)(x + (size_t)tok * D_MODEL);
    float4 v = xv[tid];
    float s  = v.x + v.y + v.z + v.w;
    float sq = v.x*v.x + v.y*v.y + v.z*v.z + v.w*v.w;
    #pragma unroll
    for (int off = 16; off; off >>= 1) {
        s  += __shfl_xor_sync(0xffffffffu, s,  off);
        sq += __shfl_xor_sync(0xffffffffu, sq, off);
    }
    __shared__ float ss[4], ssq[4];
    if ((tid & 31) == 0) { ss[tid >> 5] = s; ssq[tid >> 5] = sq; }
    __syncthreads();
    s  = ss[0]  + ss[1]  + ss[2]  + ss[3];
    sq = ssq[0] + ssq[1] + ssq[2] + ssq[3];
    float mu  = s * (1.0f / D_MODEL);
    float var = sq * (1.0f / D_MODEL) - mu * mu;
    float inv = rsqrtf(var + EPS);
    float4 wv = ((const float4*)w)[tid];
    float4 bv = ((const float4*)b)[tid];
    float o0 = (v.x - mu) * inv * wv.x + bv.x;
    float o1 = (v.y - mu) * inv * wv.y + bv.y;
    float o2 = (v.z - mu) * inv * wv.z + bv.z;
    float o3 = (v.w - mu) * inv * wv.w + bv.w;
    split_store4(oh, ol, (size_t)tok * D_MODEL + tid * 4, o0, o1, o2, o3);
}

// ================= wmma (HMMA) GEMM: C = epi(A @ Wt^T + bias) =================
// A: [M][K] bf16 hi/lo (row-major). Wt: [N][K] bf16 hi/lo (K contiguous).
// 3-term bf16 split: hi*hi + hi*lo + lo*hi, fp32 accum.
// EPI: 0 = bias -> Cf ; 1 = gelu(bias) -> Ch/Cl ; 2 = bias + res -> Cf
#define BM 128
#define BN 128
#define BKC 32
#define LDS_PAD 40                         // elements per row in smem (80B stride)
#define TILE_BYTES (128 * LDS_PAD * 2)     // 10240
#define SOFF_A_HI 0
#define SOFF_A_LO (1 * TILE_BYTES)
#define SOFF_B_HI (2 * TILE_BYTES)
#define SOFF_B_LO (3 * TILE_BYTES)
#define BUF_BYTES (4 * TILE_BYTES)         // 40960
#define GEMM_SMEM (2 * BUF_BYTES)          // 81920 (epilogue stage 64KB fits inside)

__device__ __forceinline__ void g_load_chunk(
    uint32_t buf, const __nv_bfloat16* __restrict__ Ah, const __nv_bfloat16* __restrict__ Al,
    const __nv_bfloat16* __restrict__ Bh, const __nv_bfloat16* __restrict__ Bl,
    int m0, int n0, int K, int c, int tid) {
    int koff = c * BKC;
    const __nv_bfloat16* srcs[4] = {Ah, Al, Bh, Bl};
    #pragma unroll
    for (int t = 0; t < 8; t++) {
        int idx = t * 256 + tid;
        int tile = idx >> 9;             // 0..3 (512 16B-segs per tile)
        int rem  = idx & 511;
        int row  = rem >> 2;             // 0..127
        int seg  = rem & 3;              // 0..3  (8 bf16 each)
        int base = (tile < 2) ? m0 : n0;
        uint32_t dst = buf + tile * TILE_BYTES + row * (LDS_PAD * 2) + seg * 16;
        const __nv_bfloat16* src = srcs[tile] + (size_t)(base + row) * K + koff + seg * 8;
        cp16(dst, src);
    }
    CP_COMMIT();
}

template<int EPI>
__global__ __launch_bounds__(256)
void wmma_gemm(const __nv_bfloat16* __restrict__ Ah, const __nv_bfloat16* __restrict__ Al,
               const __nv_bfloat16* __restrict__ Bh, const __nv_bfloat16* __restrict__ Bl,
               const float* __restrict__ bias, const float* __restrict__ res,
               float* __restrict__ Cf, __nv_bfloat16* __restrict__ Ch,
               __nv_bfloat16* __restrict__ Cl, int M, int N, int K) {
    extern __shared__ char smem[];
    uint32_t sb = smem_u32(smem);
    int tid = threadIdx.x;
    int wid = tid >> 5;
    int wm = wid >> 1;          // 0..3 -> 32-row band
    int wn = wid & 1;           // 0..1 -> 64-col band
    int m0 = blockIdx.y * BM, n0 = blockIdx.x * BN;

    wmma::fragment<wmma::accumulator, 16, 16, 16, float> acc[2][4];
    #pragma unroll
    for (int i = 0; i < 2; i++)
        #pragma unroll
        for (int j = 0; j < 4; j++) wmma::fill_fragment(acc[i][j], 0.0f);

    int nc = K / BKC;
    g_load_chunk(sb, Ah, Al, Bh, Bl, m0, n0, K, 0, tid);

    for (int c = 0; c < nc; c++) {
        int b = c & 1;
        if (c + 1 < nc) {
            g_load_chunk(sb + (uint32_t)(b ^ 1) * BUF_BYTES, Ah, Al, Bh, Bl, m0, n0, K, c + 1, tid);
            CP_WAIT(1);
        } else {
            CP_WAIT(0);
        }
        __syncthreads();

        const __nv_bfloat16* bufp = (const __nv_bfloat16*)(smem + (size_t)b * BUF_BYTES);
        const __nv_bfloat16* As_hi = bufp;
        const __nv_bfloat16* As_lo = bufp + TILE_BYTES / 2;
        const __nv_bfloat16* Bs_hi = bufp + TILE_BYTES;
        const __nv_bfloat16* Bs_lo = bufp + TILE_BYTES * 3 / 2;

        #pragma unroll
        for (int ks = 0; ks < 2; ks++) {
            int ko = ks * 16;
            wmma::fragment<wmma::matrix_a, 16, 16, 16, __nv_bfloat16, wmma::row_major> a_hi[2], a_lo[2];
            wmma::fragment<wmma::matrix_b, 16, 16, 16, __nv_bfloat16, wmma::col_major> b_hi[4], b_lo[4];
            #pragma unroll
            for (int i = 0; i < 2; i++) {
                int r = wm * 32 + i * 16;
                wmma::load_matrix_sync(a_hi[i], As_hi + r * LDS_PAD + ko, LDS_PAD);
                wmma::load_matrix_sync(a_lo[i], As_lo + r * LDS_PAD + ko, LDS_PAD);
            }
            #pragma unroll
            for (int j = 0; j < 4; j++) {
                int cn = wn * 64 + j * 16;
                wmma::load_matrix_sync(b_hi[j], Bs_hi + cn * LDS_PAD + ko, LDS_PAD);
                wmma::load_matrix_sync(b_lo[j], Bs_lo + cn * LDS_PAD + ko, LDS_PAD);
            }
            #pragma unroll
            for (int i = 0; i < 2; i++)
                #pragma unroll
                for (int j = 0; j < 4; j++) {
                    wmma::mma_sync(acc[i][j], a_hi[i], b_hi[j], acc[i][j]);
                    wmma::mma_sync(acc[i][j], a_hi[i], b_lo[j], acc[i][j]);
                    wmma::mma_sync(acc[i][j], a_lo[i], b_hi[j], acc[i][j]);
                }
        }
        __syncthreads();   // protect buffer b before reuse at c+2
    }

    // stage C in smem (reuse buffers): [128][128] floats = 64KB
    float* Csm = (float*)smem;
    #pragma unroll
    for (int i = 0; i < 2; i++)
        #pragma unroll
        for (int j = 0; j < 4; j++)
            wmma::store_matrix_sync(Csm + (wm * 32 + i * 16) * BN + wn * 64 + j * 16,
                                    acc[i][j], BN, wmma::mem_row_major);
    __syncthreads();

    // epilogue: 4096 float4 / 256 threads = 16 each
    #pragma unroll 4
    for (int t = 0; t < 16; t++) {
        int f = t * 256 + tid;
        int row = f >> 5;
        int cs  = (f & 31) << 2;
        float4 cv = *(float4*)&Csm[row * BN + cs];
        float4 bb = *(const float4*)&bias[n0 + cs];
        float c0 = cv.x + bb.x, c1 = cv.y + bb.y, c2 = cv.z + bb.z, c3 = cv.w + bb.w;
        size_t idx = (size_t)(m0 + row) * N + n0 + cs;
        if (EPI == 2) {
            float4 rr = *(const float4*)&res[idx];
            c0 += rr.x; c1 += rr.y; c2 += rr.z; c3 += rr.w;
        }
        if (EPI == 1) {
            c0 = gelu_exact(c0); c1 = gelu_exact(c1);
            c2 = gelu_exact(c2); c3 = gelu_exact(c3);
            split_store4(Ch, Cl, idx, c0, c1, c2, c3);
        } else {
            *(float4*)&Cf[idx] = make_float4(c0, c1, c2, c3);
        }
    }
}

// ================= Flash attention with additive bias =================
#define FL_PAD 68
__global__ __launch_bounds__(256)
void flash_kernel(const float* __restrict__ Q, const float* __restrict__ Kv,
                  const float* __restrict__ V, const float* __restrict__ bias,
                  __nv_bfloat16* __restrict__ Oh, __nv_bfloat16* __restrict__ Ol) {
    extern __shared__ float sm[];
    float* Qt = sm;
    float* Kt = Qt + 64 * FL_PAD;
    float* Vs = Kt + 64 * FL_PAD;
    float* S  = Vs + 64 * 64;

    int qt = blockIdx.x, h = blockIdx.y, b = blockIdx.z;
    int tid = threadIdx.x;
    int q0 = qt * 64;
    int ty = tid >> 4, tx = tid & 15;
    int r0 = ty << 2, c0 = tx << 2;

    {
        int r = tid >> 2;
        int dg = (tid & 3) << 4;
        const float* qrow = Q + ((size_t)(b * SEQ + q0 + r)) * D_MODEL + h * HEAD_DIM;
        #pragma unroll
        for (int ii = 0; ii < 4; ii++) {
            float4 v = *(const float4*)(qrow + dg + ii * 4);
            int d = dg + ii * 4;
            Qt[(d + 0) * FL_PAD + r] = v.x;
            Qt[(d + 1) * FL_PAD + r] = v.y;
            Qt[(d + 2) * FL_PAD + r] = v.z;
            Qt[(d + 3) * FL_PAD + r] = v.w;
        }
    }

    float m_i[4], l_i[4], o_acc[4][4];
    #pragma unroll
    for (int i = 0; i < 4; i++) {
        m_i[i] = -1e30f; l_i[i] = 0.0f;
        #pragma unroll
        for (int j = 0; j < 4; j++) o_acc[i][j] = 0.0f;
    }
    const float scale = 0.125f;

    for (int k0 = 0; k0 < SEQ; k0 += 64) {
        __syncthreads();
        {
            int r = tid >> 2;
            int dg = (tid & 3) << 4;
            const float* krow = Kv + ((size_t)(b * SEQ + k0 + r)) * D_MODEL + h * HEAD_DIM;
            const float* vrow = V  + ((size_t)(b * SEQ + k0 + r)) * D_MODEL + h * HEAD_DIM;
            #pragma unroll
            for (int ii = 0; ii < 4; ii++) {
                int d = dg + ii * 4;
                float4 kv = *(const float4*)(krow + d);
                Kt[(d + 0) * FL_PAD + r] = kv.x;
                Kt[(d + 1) * FL_PAD + r] = kv.y;
                Kt[(d + 2) * FL_PAD + r] = kv.z;
                Kt[(d + 3) * FL_PAD + r] = kv.w;
                float4 vv = *(const float4*)(vrow + d);
                *(float4*)&Vs[r * 64 + d] = vv;
            }
        }
        __syncthreads();

        float acc[4][4];
        #pragma unroll
        for (int i = 0; i < 4; i++)
            #pragma unroll
            for (int j = 0; j < 4; j++) acc[i][j] = 0.0f;
        #pragma unroll 8
        for (int d = 0; d < HEAD_DIM; d++) {
            float4 a = *(float4*)&Qt[d * FL_PAD + r0];
            float4 bb = *(float4*)&Kt[d * FL_PAD + c0];
            float av[4] = {a.x, a.y, a.z, a.w};
            float bvv[4] = {bb.x, bb.y, bb.z, bb.w};
            #pragma unroll
            for (int i = 0; i < 4; i++)
                #pragma unroll
                for (int j = 0; j < 4; j++)
                    acc[i][j] += av[i] * bvv[j];
        }

        float alpha[4];
        #pragma unroll
        for (int i = 0; i < 4; i++) {
            const float* brow = bias + ((size_t)h * SEQ + (q0 + r0 + i)) * SEQ + k0 + c0;
            float4 bb = *(const float4*)brow;
            float s0 = acc[i][0] * scale + bb.x;
            float s1 = acc[i][1] * scale + bb.y;
            float s2 = acc[i][2] * scale + bb.z;
            float s3 = acc[i][3] * scale + bb.w;
            float mx = fmaxf(fmaxf(s0, s1), fmaxf(s2, s3));
            #pragma unroll
            for (int off = 1; off < 16; off <<= 1)
                mx = fmaxf(mx, __shfl_xor_sync(0xffffffffu, mx, off));
            float m_new = fmaxf(m_i[i], mx);
            float al = __expf(m_i[i] - m_new);
            s0 = __expf(s0 - m_new);
            s1 = __expf(s1 - m_new);
            s2 = __expf(s2 - m_new);
            s3 = __expf(s3 - m_new);
            float sum = s0 + s1 + s2 + s3;
            #pragma unroll
            for (int off = 1; off < 16; off <<= 1)
                sum += __shfl_xor_sync(0xffffffffu, sum, off);
            l_i[i] = l_i[i] * al + sum;
            m_i[i] = m_new;
            alpha[i] = al;
            *(float4*)&S[(r0 + i) * FL_PAD + c0] = make_float4(s0, s1, s2, s3);
        }
        #pragma unroll
        for (int i = 0; i < 4; i++)
            #pragma unroll
            for (int j = 0; j < 4; j++) o_acc[i][j] *= alpha[i];
        __syncthreads();

        #pragma unroll 2
        for (int j = 0; j < 64; j += 4) {
            float sv[4][4];
            #pragma unroll
            for (int i = 0; i < 4; i++)
                *(float4*)sv[i] = *(float4*)&S[(r0 + i) * FL_PAD + j];
            #pragma unroll
            for (int jj = 0; jj < 4; jj++) {
                float4 v = *(float4*)&Vs[(j + jj) * 64 + c0];
                #pragma unroll
                for (int i = 0; i < 4; i++) {
                    float p = sv[i][jj];
                    o_acc[i][0] += p * v.x;
                    o_acc[i][1] += p * v.y;
                    o_acc[i][2] += p * v.z;
                    o_acc[i][3] += p * v.w;
                }
            }
        }
    }

    #pragma unroll
    for (int i = 0; i < 4; i++) {
        float invl = 1.0f / l_i[i];
        size_t idx = ((size_t)(b * SEQ + q0 + r0 + i)) * D_MODEL + h * HEAD_DIM + c0;
        split_store4(Oh, Ol, idx,
                     o_acc[i][0] * invl, o_acc[i][1] * invl,
                     o_acc[i][2] * invl, o_acc[i][3] * invl);
    }
}

// ================= launch =================
extern "C" void kernel_launch(void* const* d_in, const int* in_sizes, int n_in,
                              void* d_out, int out_size) {
    const float* x    = (const float*)d_in[0];
    const float* ab   = (const float*)d_in[1];
    const float* ln1w = (const float*)d_in[2];
    const float* ln1b = (const float*)d_in[3];
    const float* ln2w = (const float*)d_in[4];
    const float* ln2b = (const float*)d_in[5];
    const float* wq   = (const float*)d_in[6];
    const float* bq   = (const float*)d_in[7];
    const float* wk   = (const float*)d_in[8];
    const float* bk   = (const float*)d_in[9];
    const float* wv   = (const float*)d_in[10];
    const float* bv   = (const float*)d_in[11];
    const float* wo   = (const float*)d_in[12];
    const float* bo   = (const float*)d_in[13];
    const float* w1   = (const float*)d_in[14];
    const float* b1   = (const float*)d_in[15];
    const float* w2   = (const float*)d_in[16];
    const float* b2   = (const float*)d_in[17];
    float* out = (float*)d_out;

    float *q, *k, *v, *x1;
    cudaGetSymbolAddress((void**)&q,  g_q);
    cudaGetSymbolAddress((void**)&k,  g_k);
    cudaGetSymbolAddress((void**)&v,  g_v);
    cudaGetSymbolAddress((void**)&x1, g_x1);
    __nv_bfloat16 *hh, *hl, *oh, *ol, *h2h, *h2l, *ffh, *ffl;
    cudaGetSymbolAddress((void**)&hh,  g_h_hi);  cudaGetSymbolAddress((void**)&hl,  g_h_lo);
    cudaGetSymbolAddress((void**)&oh,  g_o_hi);  cudaGetSymbolAddress((void**)&ol,  g_o_lo);
    cudaGetSymbolAddress((void**)&h2h, g_h2_hi); cudaGetSymbolAddress((void**)&h2l, g_h2_lo);
    cudaGetSymbolAddress((void**)&ffh, g_ff_hi); cudaGetSymbolAddress((void**)&ffl, g_ff_lo);
    __nv_bfloat16 *wqh,*wql,*wkh,*wkl,*wvh,*wvl,*woh,*wol,*w1h,*w1l,*w2h,*w2l;
    cudaGetSymbolAddress((void**)&wqh, g_wqt_hi); cudaGetSymbolAddress((void**)&wql, g_wqt_lo);
    cudaGetSymbolAddress((void**)&wkh, g_wkt_hi); cudaGetSymbolAddress((void**)&wkl, g_wkt_lo);
    cudaGetSymbolAddress((void**)&wvh, g_wvt_hi); cudaGetSymbolAddress((void**)&wvl, g_wvt_lo);
    cudaGetSymbolAddress((void**)&woh, g_wot_hi); cudaGetSymbolAddress((void**)&wol, g_wot_lo);
    cudaGetSymbolAddress((void**)&w1h, g_w1t_hi); cudaGetSymbolAddress((void**)&w1l, g_w1t_lo);
    cudaGetSymbolAddress((void**)&w2h, g_w2t_hi); cudaGetSymbolAddress((void**)&w2l, g_w2t_lo);

    const int FLASH_SMEM = (3 * 64 * FL_PAD + 64 * 64) * (int)sizeof(float);
    cudaFuncSetAttribute(flash_kernel, cudaFuncAttributeMaxDynamicSharedMemorySize, FLASH_SMEM);
    cudaFuncSetAttribute(wmma_gemm<0>, cudaFuncAttributeMaxDynamicSharedMemorySize, GEMM_SMEM);
    cudaFuncSetAttribute(wmma_gemm<1>, cudaFuncAttributeMaxDynamicSharedMemorySize, GEMM_SMEM);
    cudaFuncSetAttribute(wmma_gemm<2>, cudaFuncAttributeMaxDynamicSharedMemorySize, GEMM_SMEM);

    // weight prep (transpose + bf16 hi/lo split)
    dim3 tw(D_MODEL / 32, D_MODEL / 32);
    convert_w<<<tw, 256>>>(wq, wqh, wql, D_MODEL, D_MODEL);
    convert_w<<<tw, 256>>>(wk, wkh, wkl, D_MODEL, D_MODEL);
    convert_w<<<tw, 256>>>(wv, wvh, wvl, D_MODEL, D_MODEL);
    convert_w<<<tw, 256>>>(wo, woh, wol, D_MODEL, D_MODEL);
    convert_w<<<dim3(D_MODEL / 32, D_FF / 32), 256>>>(w1, w1h, w1l, D_MODEL, D_FF);
    convert_w<<<dim3(D_FF / 32, D_MODEL / 32), 256>>>(w2, w2h, w2l, D_FF, D_MODEL);

    dim3 gD(D_MODEL / BN, NTOK / BM);   // (4, 64)
    dim3 gF(D_FF / BN,   NTOK / BM);    // (16, 64)

    // 1. h = LN1(x)  (bf16 hi/lo)
    ln_kernel<<<NTOK, 128>>>(x, ln1w, ln1b, hh, hl);
    // 2-4. q,k,v = h @ w{q,k,v} + b  (fp32 out for flash)
    wmma_gemm<0><<<gD, 256, GEMM_SMEM>>>(hh, hl, wqh, wql, bq, nullptr, q, nullptr, nullptr, NTOK, D_MODEL, D_MODEL);
    wmma_gemm<0><<<gD, 256, GEMM_SMEM>>>(hh, hl, wkh, wkl, bk, nullptr, k, nullptr, nullptr, NTOK, D_MODEL, D_MODEL);
    wmma_gemm<0><<<gD, 256, GEMM_SMEM>>>(hh, hl, wvh, wvl, bv, nullptr, v, nullptr, nullptr, NTOK, D_MODEL, D_MODEL);
    // 5. attention -> o (bf16 hi/lo)
    flash_kernel<<<dim3(SEQ / 64, NHEAD, BATCH), 256, FLASH_SMEM>>>(q, k, v, ab, oh, ol);
    // 6. x1 = x + o @ wo + bo
    wmma_gemm<2><<<gD, 256, GEMM_SMEM>>>(oh, ol, woh, wol, bo, x, x1, nullptr, nullptr, NTOK, D_MODEL, D_MODEL);
    // 7. h2 = LN2(x1)
    ln_kernel<<<NTOK, 128>>>(x1, ln2w, ln2b, h2h, h2l);
    // 8. ff = GELU(h2 @ w1 + b1)  (bf16 hi/lo)
    wmma_gemm<1><<<gF, 256, GEMM_SMEM>>>(h2h, h2l, w1h, w1l, b1, nullptr, nullptr, ffh, ffl, NTOK, D_FF, D_MODEL);
    // 9. out = x1 + ff @ w2 + b2
    wmma_gemm<2><<<gD, 256, GEMM_SMEM>>>(ffh, ffl, w2h, w2l, b2, x1, out, nullptr, nullptr, NTOK, D_MODEL, D_FF);
}